// round 16
// baseline (speedup 1.0000x reference)
#include <cuda_runtime.h>
#include <cstdint>
#include <math.h>

// Problem constants
#define T_TOK 4096      // B*S
#define HDIM  1024
#define IDIM  2816
#define EDIM  8
#define TOPK  2
#define NPAIR (T_TOK*TOPK)   // 8192

#define KC    32        // K-chunk per stage
#define BMT   128       // CTA M tile
#define PADA  36        // A smem row pitch (floats)
#define A_FL  (BMT*PADA)   // 4608 floats

// fused gate+up tile
#define BN_GU   64
#define PADB_GU 72          // 64 + 8 pad: (72*kq+nq)%32 = 8kq+nq unique -> conflict-free
#define B_FL_GU (KC*PADB_GU)   // 2304 floats per matrix

// down tile
#define BN_DN   128
#define PADB_DN 136
#define B_FL_DN (KC*PADB_DN)   // 4352 floats

// x pre-rounding (fused into router launch)
#define XQ (T_TOK*HDIM/4)
#define XQ_PER_BLK (128*8)
#define XBLKS (XQ/XQ_PER_BLK)  // 1024

// ---------------- scratch (__device__ globals: alloc-free) ----------------
__device__ int   g_cnt[EDIM];
__device__ int   g_off[EDIM + 1];
__device__ int   g_fill[EDIM];
__device__ int   g_tok_e[NPAIR];
__device__ float g_tok_w[NPAIR];
__device__ int   g_list[NPAIR];
__device__ float g_wt[NPAIR];
__device__ int   g_tokpair[NPAIR];
__device__ float g_xr[(size_t)T_TOK * HDIM];       // tf32-rounded x
__device__ float g_act[(size_t)NPAIR * IDIM];      // swiglu acts (tf32-rounded)
__device__ float g_pairout[(size_t)NPAIR * HDIM];

// ---------------- helpers ----------------
__device__ __forceinline__ uint32_t f2tf32(float f) {
    uint32_t r;
    asm("cvt.rna.tf32.f32 %0, %1;" : "=r"(r) : "f"(f));
    return r;
}
__device__ __forceinline__ float tf32f(float f) {
    return __uint_as_float(f2tf32(f));
}
__device__ __forceinline__ void mma_tf32(float* d, const uint32_t* a, const uint32_t* b) {
    asm volatile(
        "mma.sync.aligned.m16n8k8.row.col.f32.tf32.tf32.f32 "
        "{%0,%1,%2,%3}, {%4,%5,%6,%7}, {%8,%9}, {%0,%1,%2,%3};"
        : "+f"(d[0]), "+f"(d[1]), "+f"(d[2]), "+f"(d[3])
        : "r"(a[0]), "r"(a[1]), "r"(a[2]), "r"(a[3]), "r"(b[0]), "r"(b[1]));
}
__device__ __forceinline__ uint32_t smem_u32(const void* p) {
    uint32_t a;
    asm("{ .reg .u64 t; cvta.to.shared.u64 t, %1; cvt.u32.u64 %0, t; }" : "=r"(a) : "l"(p));
    return a;
}
__device__ __forceinline__ void cp16(uint32_t dst, const void* src) {
    asm volatile("cp.async.ca.shared.global [%0], [%1], 16;" :: "r"(dst), "l"(src));
}
#define CP_COMMIT() asm volatile("cp.async.commit_group;" ::: "memory")
#define CP_WAIT0()  asm volatile("cp.async.wait_group 0;" ::: "memory")

// ---------------- router + x pre-rounding (fused launch #1) ----------------
__global__ void router_kernel(const float* __restrict__ x,
                              const float* __restrict__ gw,
                              float* __restrict__ out_logits) {
    if (blockIdx.x >= T_TOK) {
        int b = blockIdx.x - T_TOK;
        const float4* src = (const float4*)x;
        float4* dst = (float4*)g_xr;
        int base = b * XQ_PER_BLK + threadIdx.x;
#pragma unroll
        for (int it = 0; it < 8; it++) {
            int i = base + it * 128;
            float4 v = src[i];
            v.x = tf32f(v.x); v.y = tf32f(v.y);
            v.z = tf32f(v.z); v.w = tf32f(v.w);
            dst[i] = v;
        }
        return;
    }

    const int t = blockIdx.x;
    const int tid = threadIdx.x;
    float acc[EDIM];
#pragma unroll
    for (int e = 0; e < EDIM; e++) acc[e] = 0.f;
    const float* xr = x + (size_t)t * HDIM;
    for (int h = tid; h < HDIM; h += 128) {
        float xv = xr[h];
        const float* gr = gw + (size_t)h * EDIM;
#pragma unroll
        for (int e = 0; e < EDIM; e++) acc[e] += xv * gr[e];
    }
    __shared__ float red[EDIM][128];
#pragma unroll
    for (int e = 0; e < EDIM; e++) red[e][tid] = acc[e];
    __syncthreads();
    for (int s = 64; s > 0; s >>= 1) {
        if (tid < s) {
#pragma unroll
            for (int e = 0; e < EDIM; e++) red[e][tid] += red[e][tid + s];
        }
        __syncthreads();
    }
    if (tid == 0) {
        float l[EDIM];
#pragma unroll
        for (int e = 0; e < EDIM; e++) {
            l[e] = red[e][0];
            out_logits[(size_t)t * EDIM + e] = l[e];
        }
        int i0 = 0;
#pragma unroll
        for (int e = 1; e < EDIM; e++) if (l[e] > l[i0]) i0 = e;
        int i1 = -1;
#pragma unroll
        for (int e = 0; e < EDIM; e++) {
            if (e == i0) continue;
            if (i1 < 0 || l[e] > l[i1]) i1 = e;
        }
        float e1 = expf(l[i1] - l[i0]);
        float w0 = 1.f / (1.f + e1);
        float w1 = e1 / (1.f + e1);
        g_tok_e[t * 2 + 0] = i0; g_tok_w[t * 2 + 0] = w0;
        g_tok_e[t * 2 + 1] = i1; g_tok_w[t * 2 + 1] = w1;
        atomicAdd(&g_cnt[i0], 1);
        atomicAdd(&g_cnt[i1], 1);
    }
}

__global__ void scan_kernel() {
    int s = 0;
    for (int e = 0; e < EDIM; e++) {
        g_off[e] = s;
        s += g_cnt[e];
        g_fill[e] = 0;
        g_cnt[e] = 0;
    }
    g_off[EDIM] = s;
}

__global__ void assign_kernel() {
    int t = blockIdx.x * blockDim.x + threadIdx.x;
    if (t >= T_TOK) return;
#pragma unroll
    for (int k = 0; k < TOPK; k++) {
        int e = g_tok_e[t * 2 + k];
        int slot = atomicAdd(&g_fill[e], 1);
        int p = g_off[e] + slot;
        g_list[p] = t;
        g_wt[p] = g_tok_w[t * 2 + k];
        g_tokpair[t * 2 + k] = p;
    }
}

// ============================================================================
// FUSED gate+up GEMM: CTA 128x64, both weight matrices per tile, A fragments
// shared by both MMA streams. A: cp.async double-buffered from g_xr (pre-
// rounded, no cvt in loop). Bg/Bu: reg-prefetch LDG -> cvt -> STS, one stage.
// Epilogue applies SwiGLU on registers, writes tf32-rounded g_act directly.
// ============================================================================
#define GU_SMEM ((128 + 2 * A_FL + 2 * B_FL_GU) * 4)

__global__ __launch_bounds__(256, 2) void gateup_tc(
    const float* __restrict__ Wg, const float* __restrict__ Wu) {
    extern __shared__ float sm[];
    const int e = blockIdx.z;
    const int ne = g_off[e + 1] - g_off[e];
    const int m0 = blockIdx.y * BMT;
    if (m0 >= ne) return;
    const int n0 = blockIdx.x * BN_GU;
    const int off = g_off[e];

    int* rowtok = (int*)sm;
    const int tid = threadIdx.x;
    const int wid = tid >> 5;
    const int lane = tid & 31;
    if (tid < BMT) {
        int m = m0 + tid;
        rowtok[tid] = g_list[off + (m < ne ? m : 0)];
    }
    __syncthreads();

    // A source pointers (pre-rounded)
    const float* aptr[4];
#pragma unroll
    for (int i = 0; i < 4; i++) {
        int r = i * 32 + (tid >> 3);
        aptr[i] = g_xr + (size_t)rowtok[r] * HDIM + (tid & 7) * 4;
    }
    // B: per thread col4 = (tid&15)*4, rows (tid>>4) and (tid>>4)+16
    const int bc4 = (tid & 15) * 4;
    const int brr = tid >> 4;       // 0..15
    const float* bpg = Wg + (size_t)e * HDIM * IDIM + (size_t)brr * IDIM + n0 + bc4;
    const float* bpu = Wu + (size_t)e * HDIM * IDIM + (size_t)brr * IDIM + n0 + bc4;

    float* sA[2] = { sm + 128, sm + 128 + A_FL };
    float* sBg = sm + 128 + 2 * A_FL;
    float* sBu = sBg + B_FL_GU;
    const uint32_t su = smem_u32(sm + 128);
    const uint32_t sAu[2] = { su, su + A_FL * 4 };
    const uint32_t aoff = ((uint32_t)(tid >> 3) * PADA + (tid & 7) * 4) * 4;

    const int m0w = (wid >> 2) * 64;
    const int n0w = (wid & 3) * 16;
    const int r0 = lane >> 2;
    const int kq = lane & 3;
    const int nq = lane >> 2;

    float accg[4][2][4], accu[4][2][4];
#pragma unroll
    for (int i = 0; i < 4; i++)
#pragma unroll
        for (int j = 0; j < 2; j++)
#pragma unroll
            for (int q = 0; q < 4; q++) { accg[i][j][q] = 0.f; accu[i][j][q] = 0.f; }

    float4 vg[2], vu[2];
    // prologue
#pragma unroll
    for (int i = 0; i < 4; i++)
        cp16(sAu[0] + aoff + (uint32_t)(i * 32 * PADA * 4), aptr[i]);
    CP_COMMIT();
    vg[0] = *(const float4*)(bpg);
    vg[1] = *(const float4*)(bpg + (size_t)16 * IDIM);
    vu[0] = *(const float4*)(bpu);
    vu[1] = *(const float4*)(bpu + (size_t)16 * IDIM);
    CP_WAIT0();

    const int NCH = HDIM / KC;  // 32
#pragma unroll 1
    for (int kc = 0; kc < NCH; kc++) {
        const int buf = kc & 1;
        const bool more = (kc + 1 < NCH);

        // stage B(kc) from prefetched regs (cvt off the critical path)
#pragma unroll
        for (int i = 0; i < 2; i++) {
            float* dg = sBg + (brr + i * 16) * PADB_GU + bc4;
            float4 v = vg[i];
            dg[0] = tf32f(v.x); dg[1] = tf32f(v.y); dg[2] = tf32f(v.z); dg[3] = tf32f(v.w);
            float* du = sBu + (brr + i * 16) * PADB_GU + bc4;
            v = vu[i];
            du[0] = tf32f(v.x); du[1] = tf32f(v.y); du[2] = tf32f(v.z); du[3] = tf32f(v.w);
        }
        __syncthreads();

        // issue next-chunk loads
        if (more) {
            const int k0n = (kc + 1) * KC;
#pragma unroll
            for (int i = 0; i < 4; i++)
                cp16(sAu[buf ^ 1] + aoff + (uint32_t)(i * 32 * PADA * 4),
                     aptr[i] + k0n);
            CP_COMMIT();
            const float* bng = bpg + (size_t)k0n * IDIM;
            const float* bnu = bpu + (size_t)k0n * IDIM;
            vg[0] = *(const float4*)(bng);
            vg[1] = *(const float4*)(bng + (size_t)16 * IDIM);
            vu[0] = *(const float4*)(bnu);
            vu[1] = *(const float4*)(bnu + (size_t)16 * IDIM);
        }

        // compute: A fragments shared by gate and up MMA streams
        const float* cA = sA[buf];
#pragma unroll
        for (int k8 = 0; k8 < KC; k8 += 8) {
            uint32_t af[4][4];
#pragma unroll
            for (int mt = 0; mt < 4; mt++) {
                const float* ab = cA + (m0w + mt * 16 + r0) * PADA + k8 + kq;
                af[mt][0] = __float_as_uint(ab[0]);
                af[mt][1] = __float_as_uint(ab[8 * PADA]);
                af[mt][2] = __float_as_uint(ab[4]);
                af[mt][3] = __float_as_uint(ab[8 * PADA + 4]);
            }
#pragma unroll
            for (int nt = 0; nt < 2; nt++) {
                const float* gb = sBg + (k8 + kq) * PADB_GU + n0w + nt * 8 + nq;
                uint32_t bg[2] = { __float_as_uint(gb[0]), __float_as_uint(gb[4 * PADB_GU]) };
                const float* ub = sBu + (k8 + kq) * PADB_GU + n0w + nt * 8 + nq;
                uint32_t bu[2] = { __float_as_uint(ub[0]), __float_as_uint(ub[4 * PADB_GU]) };
#pragma unroll
                for (int mt = 0; mt < 4; mt++) {
                    mma_tf32(accg[mt][nt], af[mt], bg);
                    mma_tf32(accu[mt][nt], af[mt], bu);
                }
            }
        }
        if (more) CP_WAIT0();
        __syncthreads();
    }

    // epilogue: SwiGLU on registers -> tf32-rounded g_act
#pragma unroll
    for (int mt = 0; mt < 4; mt++) {
        int rloc = m0w + mt * 16 + (lane >> 2);
#pragma unroll
        for (int h = 0; h < 2; h++) {
            int m = m0 + rloc + h * 8;
            if (m < ne) {
                float* orow = g_act + (size_t)(off + m) * IDIM + n0;
#pragma unroll
                for (int nt = 0; nt < 2; nt++) {
                    int c = n0w + nt * 8 + 2 * (lane & 3);
                    float gg0 = accg[mt][nt][2 * h], gg1 = accg[mt][nt][2 * h + 1];
                    float2 v;
                    v.x = tf32f(gg0 / (1.f + expf(-gg0)) * accu[mt][nt][2 * h]);
                    v.y = tf32f(gg1 / (1.f + expf(-gg1)) * accu[mt][nt][2 * h + 1]);
                    *(float2*)(orow + c) = v;
                }
            }
        }
    }
}

// ============================================================================
// down GEMM (unchanged R14 core): cp.async pre-rounded A, reg-prefetch B.
// ============================================================================
#define DN_SMEM ((128 + 2 * A_FL + B_FL_DN) * 4)

__global__ __launch_bounds__(256, 2) void down_tc(const float* __restrict__ Wd) {
    extern __shared__ float sm[];
    const int e = blockIdx.z;
    const int ne = g_off[e + 1] - g_off[e];
    const int m0 = blockIdx.y * BMT;
    if (m0 >= ne) return;
    const int n0 = blockIdx.x * BN_DN;
    const int off = g_off[e];

    const int tid = threadIdx.x;
    const int wid = tid >> 5;
    const int lane = tid & 31;

    const float* aptr[4];
#pragma unroll
    for (int i = 0; i < 4; i++) {
        int r = i * 32 + (tid >> 3);
        int idx = off + m0 + r;
        if (idx >= NPAIR) idx = NPAIR - 1;
        aptr[i] = g_act + (size_t)idx * IDIM + (tid & 7) * 4;   // pre-rounded
    }
    const int bc4 = (tid & 31) * 4;
    const int br  = tid >> 5;
    const float* bp = Wd + (size_t)e * IDIM * HDIM + (size_t)br * HDIM + n0 + bc4;

    float* sA[2] = { sm + 128, sm + 128 + A_FL };
    float* sB = sm + 128 + 2 * A_FL;
    const uint32_t su = smem_u32(sm + 128);
    const uint32_t sAu[2] = { su, su + A_FL * 4 };
    const uint32_t aoff = ((uint32_t)(tid >> 3) * PADA + (tid & 7) * 4) * 4;

    const int m0w = (wid >> 2) * 64;
    const int n0w = (wid & 3) * 32;
    const int r0 = lane >> 2;
    const int kq = lane & 3;
    const int nq = lane >> 2;

    float acc[4][4][4];
#pragma unroll
    for (int i = 0; i < 4; i++)
#pragma unroll
        for (int j = 0; j < 4; j++)
#pragma unroll
            for (int q = 0; q < 4; q++) acc[i][j][q] = 0.f;

    float4 vb[4];
#pragma unroll
    for (int i = 0; i < 4; i++)
        cp16(sAu[0] + aoff + (uint32_t)(i * 32 * PADA * 4), aptr[i]);
    CP_COMMIT();
#pragma unroll
    for (int i = 0; i < 4; i++)
        vb[i] = *(const float4*)(bp + (size_t)(i * 8) * HDIM);
    CP_WAIT0();

    const int NCH = IDIM / KC;  // 88
#pragma unroll 1
    for (int kc = 0; kc < NCH; kc++) {
        const int buf = kc & 1;
        const bool more = (kc + 1 < NCH);

#pragma unroll
        for (int i = 0; i < 4; i++) {
            float* db = sB + (i * 8 + br) * PADB_DN + bc4;
            db[0] = tf32f(vb[i].x); db[1] = tf32f(vb[i].y);
            db[2] = tf32f(vb[i].z); db[3] = tf32f(vb[i].w);
        }
        __syncthreads();

        if (more) {
            const int k0n = (kc + 1) * KC;
#pragma unroll
            for (int i = 0; i < 4; i++)
                cp16(sAu[buf ^ 1] + aoff + (uint32_t)(i * 32 * PADA * 4),
                     aptr[i] + k0n);
            CP_COMMIT();
            const float* bn = bp + (size_t)k0n * HDIM;
#pragma unroll
            for (int i = 0; i < 4; i++)
                vb[i] = *(const float4*)(bn + (size_t)(i * 8) * HDIM);
        }

        const float* cA = sA[buf];
#pragma unroll
        for (int k8 = 0; k8 < KC; k8 += 8) {
            uint32_t af[4][4];
#pragma unroll
            for (int mt = 0; mt < 4; mt++) {
                const float* ab = cA + (m0w + mt * 16 + r0) * PADA + k8 + kq;
                af[mt][0] = __float_as_uint(ab[0]);
                af[mt][1] = __float_as_uint(ab[8 * PADA]);
                af[mt][2] = __float_as_uint(ab[4]);
                af[mt][3] = __float_as_uint(ab[8 * PADA + 4]);
            }
#pragma unroll
            for (int nt = 0; nt < 4; nt++) {
                const float* bb = sB + (k8 + kq) * PADB_DN + n0w + nt * 8 + nq;
                uint32_t bf[2] = { __float_as_uint(bb[0]), __float_as_uint(bb[4 * PADB_DN]) };
#pragma unroll
                for (int mt = 0; mt < 4; mt++)
                    mma_tf32(acc[mt][nt], af[mt], bf);
            }
        }
        if (more) CP_WAIT0();
        __syncthreads();
    }

#pragma unroll
    for (int mt = 0; mt < 4; mt++) {
        int rloc = m0w + mt * 16 + (lane >> 2);
#pragma unroll
        for (int h = 0; h < 2; h++) {
            int m = m0 + rloc + h * 8;
            if (m < ne) {
                float wt = g_wt[off + m];
                float* orow = g_pairout + (size_t)(off + m) * HDIM + n0;
#pragma unroll
                for (int nt = 0; nt < 4; nt++) {
                    int c = n0w + nt * 8 + 2 * (lane & 3);
                    float2 v;
                    v.x = wt * acc[mt][nt][2 * h];
                    v.y = wt * acc[mt][nt][2 * h + 1];
                    *(float2*)(orow + c) = v;
                }
            }
        }
    }
}

// out[t, :] = pairout[p0, :] + pairout[p1, :]
__global__ void combine_kernel(float* __restrict__ out) {
    int idx = blockIdx.x * blockDim.x + threadIdx.x;
    int t = idx >> 8;
    int h4 = idx & 255;
    int p0 = g_tokpair[t * 2 + 0];
    int p1 = g_tokpair[t * 2 + 1];
    const float4* po = (const float4*)g_pairout;
    float4 a = po[(size_t)p0 * 256 + h4];
    float4 b = po[(size_t)p1 * 256 + h4];
    float4 r;
    r.x = a.x + b.x; r.y = a.y + b.y; r.z = a.z + b.z; r.w = a.w + b.w;
    ((float4*)out)[idx] = r;
}

// ---------------- launch ----------------
extern "C" void kernel_launch(void* const* d_in, const int* in_sizes, int n_in,
                              void* d_out, int out_size) {
    const float* x  = (const float*)d_in[0];
    const float* gw = (const float*)d_in[1];
    const float* Wg = (const float*)d_in[2];
    const float* Wu = (const float*)d_in[3];
    const float* Wd = (const float*)d_in[4];
    float* out = (float*)d_out;
    float* out_logits = out + (size_t)T_TOK * HDIM;

    cudaFuncSetAttribute(gateup_tc, cudaFuncAttributeMaxDynamicSharedMemorySize, GU_SMEM);
    cudaFuncSetAttribute(down_tc, cudaFuncAttributeMaxDynamicSharedMemorySize, DN_SMEM);

    router_kernel<<<T_TOK + XBLKS, 128>>>(x, gw, out_logits);
    scan_kernel<<<1, 1>>>();
    assign_kernel<<<T_TOK / 256, 256>>>();
    gateup_tc<<<dim3(IDIM / BN_GU, NPAIR / BMT, EDIM), 256, GU_SMEM>>>(Wg, Wu);
    down_tc<<<dim3(HDIM / BN_DN, NPAIR / BMT, EDIM), 256, DN_SMEM>>>(Wd);
    combine_kernel<<<(T_TOK * HDIM / 4) / 256, 256>>>(out);
}

// round 17
// speedup vs baseline: 1.6640x; 1.6640x over previous
#include <cuda_runtime.h>
#include <cstdint>
#include <math.h>

// Problem constants
#define T_TOK 4096      // B*S
#define HDIM  1024
#define IDIM  2816
#define EDIM  8
#define TOPK  2
#define NPAIR (T_TOK*TOPK)   // 8192

#define KC    32        // K-chunk per stage
#define BMT   128       // CTA M tile
#define BNT   128       // CTA N tile
#define PADB  136       // B smem row pitch (floats)
#define B_FL  (KC*PADB)    // 4352 floats

// A fragment-major layout: 32 groups (rowgrp 0..7 x g 0..3), each 132 floats
// (128 data + 4 pad so staging STS spreads banks). float4 fragment for
// (group, lane) = {A[r0][kq], A[r0+8][kq], A[r0][kq+4], A[r0+8][kq+4]},
// r0 = lane>>2, kq = lane&3, rows relative to rowgrp*16, cols to g*8.
#define AF_GRP 132
#define A_FL   (32*AF_GRP)   // 4224 floats

// ---------------- scratch (__device__ globals: alloc-free) ----------------
__device__ int   g_cnt[EDIM];        // zero-init at load; scan re-zeroes each call
__device__ int   g_off[EDIM + 1];
__device__ int   g_fill[EDIM];
__device__ int   g_tok_e[NPAIR];
__device__ float g_tok_w[NPAIR];
__device__ int   g_list[NPAIR];
__device__ float g_wt[NPAIR];
__device__ int   g_tokpair[NPAIR];
__device__ float g_raw[(size_t)NPAIR * IDIM];      // raw gate GEMM out
__device__ float g_act[(size_t)NPAIR * IDIM];      // swiglu activations
__device__ float g_pairout[(size_t)NPAIR * HDIM];

// ---------------- helpers ----------------
__device__ __forceinline__ uint32_t f2tf32(float f) {
    uint32_t r;
    asm("cvt.rna.tf32.f32 %0, %1;" : "=r"(r) : "f"(f));
    return r;
}
__device__ __forceinline__ float tf32f(float f) {
    return __uint_as_float(f2tf32(f));
}
__device__ __forceinline__ void mma_tf32(float* d, const uint32_t* a, const uint32_t* b) {
    asm volatile(
        "mma.sync.aligned.m16n8k8.row.col.f32.tf32.tf32.f32 "
        "{%0,%1,%2,%3}, {%4,%5,%6,%7}, {%8,%9}, {%0,%1,%2,%3};"
        : "+f"(d[0]), "+f"(d[1]), "+f"(d[2]), "+f"(d[3])
        : "r"(a[0]), "r"(a[1]), "r"(a[2]), "r"(a[3]), "r"(b[0]), "r"(b[1]));
}

// ---------------- routing kernels ----------------
__global__ void router_kernel(const float* __restrict__ x,
                              const float* __restrict__ gw,
                              float* __restrict__ out_logits) {
    const int t = blockIdx.x;
    const int tid = threadIdx.x;
    float acc[EDIM];
#pragma unroll
    for (int e = 0; e < EDIM; e++) acc[e] = 0.f;
    const float* xr = x + (size_t)t * HDIM;
    for (int h = tid; h < HDIM; h += 128) {
        float xv = xr[h];
        const float* gr = gw + (size_t)h * EDIM;
#pragma unroll
        for (int e = 0; e < EDIM; e++) acc[e] += xv * gr[e];
    }
    __shared__ float red[EDIM][128];
#pragma unroll
    for (int e = 0; e < EDIM; e++) red[e][tid] = acc[e];
    __syncthreads();
    for (int s = 64; s > 0; s >>= 1) {
        if (tid < s) {
#pragma unroll
            for (int e = 0; e < EDIM; e++) red[e][tid] += red[e][tid + s];
        }
        __syncthreads();
    }
    if (tid == 0) {
        float l[EDIM];
#pragma unroll
        for (int e = 0; e < EDIM; e++) {
            l[e] = red[e][0];
            out_logits[(size_t)t * EDIM + e] = l[e];
        }
        int i0 = 0;
#pragma unroll
        for (int e = 1; e < EDIM; e++) if (l[e] > l[i0]) i0 = e;
        int i1 = -1;
#pragma unroll
        for (int e = 0; e < EDIM; e++) {
            if (e == i0) continue;
            if (i1 < 0 || l[e] > l[i1]) i1 = e;
        }
        float e1 = expf(l[i1] - l[i0]);
        float w0 = 1.f / (1.f + e1);
        float w1 = e1 / (1.f + e1);
        g_tok_e[t * 2 + 0] = i0; g_tok_w[t * 2 + 0] = w0;
        g_tok_e[t * 2 + 1] = i1; g_tok_w[t * 2 + 1] = w1;
        atomicAdd(&g_cnt[i0], 1);
        atomicAdd(&g_cnt[i1], 1);
    }
}

__global__ void scan_kernel() {
    int s = 0;
    for (int e = 0; e < EDIM; e++) {
        g_off[e] = s;
        s += g_cnt[e];
        g_fill[e] = 0;
        g_cnt[e] = 0;
    }
    g_off[EDIM] = s;
}

__global__ void assign_kernel() {
    int t = blockIdx.x * blockDim.x + threadIdx.x;
    if (t >= T_TOK) return;
#pragma unroll
    for (int k = 0; k < TOPK; k++) {
        int e = g_tok_e[t * 2 + k];
        int slot = atomicAdd(&g_fill[e], 1);
        int p = g_off[e] + slot;
        g_list[p] = t;
        g_wt[p] = g_tok_w[t * 2 + k];
        g_tokpair[t * 2 + k] = p;
    }
}

// ============================================================================
// GEMM mainloop core — EXACT R9 structure (single-buffer smem, A LDG at loop
// top, B reg-prefetch, 2 syncs/chunk). ONLY change: A stored fragment-major
// so inner-loop A reads are 4 conflict-free LDS128 instead of 16 LDS32.
// ============================================================================
struct GemmCore {
    static __device__ __forceinline__ void run(
        float* sA, float* sB,
        const float* aptr[4], const float* bptr, size_t ldb,
        int NCH, int tid, int wid, int lane,
        float acc[4][4][4]) {
        const int c0  = (tid & 7) * 4;       // A col base within chunk
        const int bc4 = (tid & 31) * 4;
        const int br  = tid >> 5;            // 0..7
        const int n0w = (wid & 3) * 32;
        const int kq = lane & 3;
        const int nq = lane >> 2;

        // A staging constants (fragment-major): g, half fixed per thread
        const int ag    = c0 >> 3;           // 0..3
        const int ahalf = (c0 >> 2) & 1;     // 0..1

        // per-thread B pointer
        const float* bp = bptr + (size_t)br * ldb + bc4;

        // A fragment base group for this warp's m rows: (wid>>2)*4 + mt
        const int argrp0 = (wid >> 2) * 4;

        float4 vb[4];
#pragma unroll
        for (int i = 0; i < 4; i++)
            vb[i] = *(const float4*)(bp + (size_t)(i * 8) * ldb);

#pragma unroll 1
        for (int kc = 0; kc < NCH; kc++) {
            const int k0 = kc * KC;
            // A loads + fragment-major store (cvt at STS, as in R9)
            float4 va[4];
#pragma unroll
            for (int i = 0; i < 4; i++)
                va[i] = *(const float4*)(aptr[i] + k0);
#pragma unroll
            for (int i = 0; i < 4; i++) {
                int r = i * 32 + (tid >> 3);
                int rowgrp = r >> 4;
                int r0 = r & 7;
                int hi = (r >> 3) & 1;
                float* da = sA + (rowgrp * 4 + ag) * AF_GRP + r0 * 16
                               + ahalf * 2 + hi;
                da[0]  = tf32f(va[i].x);
                da[4]  = tf32f(va[i].y);
                da[8]  = tf32f(va[i].z);
                da[12] = tf32f(va[i].w);
                // B staging unchanged (row-major padded)
                float* db = sB + (i * 8 + br) * PADB + bc4;
                db[0] = tf32f(vb[i].x); db[1] = tf32f(vb[i].y);
                db[2] = tf32f(vb[i].z); db[3] = tf32f(vb[i].w);
            }
            __syncthreads();
            // prefetch next B chunk
            if (kc + 1 < NCH) {
                const float* bn = bp + (size_t)(k0 + KC) * ldb;
#pragma unroll
                for (int i = 0; i < 4; i++)
                    vb[i] = *(const float4*)(bn + (size_t)(i * 8) * ldb);
            }
            // compute
#pragma unroll
            for (int k8 = 0; k8 < KC; k8 += 8) {
                const int g = k8 >> 3;
                uint32_t af[4][4];
#pragma unroll
                for (int mt = 0; mt < 4; mt++) {
                    float4 fr = *(const float4*)(
                        sA + ((argrp0 + mt) * 4 + g) * AF_GRP + lane * 4);
                    af[mt][0] = __float_as_uint(fr.x);
                    af[mt][1] = __float_as_uint(fr.y);
                    af[mt][2] = __float_as_uint(fr.z);
                    af[mt][3] = __float_as_uint(fr.w);
                }
#pragma unroll
                for (int nt = 0; nt < 4; nt++) {
                    const float* bb = sB + (k8 + kq) * PADB + n0w + nt * 8 + nq;
                    uint32_t bf[2] = { __float_as_uint(bb[0]), __float_as_uint(bb[4 * PADB]) };
#pragma unroll
                    for (int mt = 0; mt < 4; mt++)
                        mma_tf32(acc[mt][nt], af[mt], bf);
                }
            }
            __syncthreads();
        }
    }
};

#define GEMM_SMEM ((128 + A_FL + B_FL) * 4)   // rowtok + A(frag-major) + B

// ---------------- gate GEMM: g_raw = x[rowtok] @ Wg ----------------
__global__ __launch_bounds__(256, 2) void gate_tc(
    const float* __restrict__ x, const float* __restrict__ Wg) {
    extern __shared__ float sm[];
    const int e = blockIdx.z;
    const int ne = g_off[e + 1] - g_off[e];
    const int m0 = blockIdx.y * BMT;
    if (m0 >= ne) return;
    const int n0 = blockIdx.x * BNT;
    const int off = g_off[e];

    int* rowtok = (int*)sm;
    const int tid = threadIdx.x;
    const int wid = tid >> 5;
    const int lane = tid & 31;
    if (tid < BMT) {
        int m = m0 + tid;
        rowtok[tid] = g_list[off + (m < ne ? m : 0)];
    }
    __syncthreads();

    const float* aptr[4];
#pragma unroll
    for (int i = 0; i < 4; i++) {
        int r = i * 32 + (tid >> 3);
        aptr[i] = x + (size_t)rowtok[r] * HDIM + (tid & 7) * 4;
    }
    const float* bptr = Wg + (size_t)e * HDIM * IDIM + n0;

    float acc[4][4][4];
#pragma unroll
    for (int i = 0; i < 4; i++)
#pragma unroll
        for (int j = 0; j < 4; j++)
#pragma unroll
            for (int q = 0; q < 4; q++) acc[i][j][q] = 0.f;

    GemmCore::run(sm + 128, sm + 128 + A_FL, aptr, bptr, IDIM,
                  HDIM / KC, tid, wid, lane, acc);

    const int m0w = (wid >> 2) * 64;
    const int n0w = (wid & 3) * 32;
#pragma unroll
    for (int mt = 0; mt < 4; mt++) {
        int rloc = m0w + mt * 16 + (lane >> 2);
#pragma unroll
        for (int h = 0; h < 2; h++) {
            int m = m0 + rloc + h * 8;
            if (m < ne) {
                float* orow = g_raw + (size_t)(off + m) * IDIM + n0;
#pragma unroll
                for (int nt = 0; nt < 4; nt++) {
                    int c = n0w + nt * 8 + 2 * (lane & 3);
                    float2 v;
                    v.x = acc[mt][nt][2 * h];
                    v.y = acc[mt][nt][2 * h + 1];
                    *(float2*)(orow + c) = v;
                }
            }
        }
    }
}

// ---------------- up GEMM + SwiGLU: g_act = silu(g_raw) * (x @ Wu) ----------
__global__ __launch_bounds__(256, 2) void up_tc(
    const float* __restrict__ x, const float* __restrict__ Wu) {
    extern __shared__ float sm[];
    const int e = blockIdx.z;
    const int ne = g_off[e + 1] - g_off[e];
    const int m0 = blockIdx.y * BMT;
    if (m0 >= ne) return;
    const int n0 = blockIdx.x * BNT;
    const int off = g_off[e];

    int* rowtok = (int*)sm;
    const int tid = threadIdx.x;
    const int wid = tid >> 5;
    const int lane = tid & 31;
    if (tid < BMT) {
        int m = m0 + tid;
        rowtok[tid] = g_list[off + (m < ne ? m : 0)];
    }
    __syncthreads();

    const float* aptr[4];
#pragma unroll
    for (int i = 0; i < 4; i++) {
        int r = i * 32 + (tid >> 3);
        aptr[i] = x + (size_t)rowtok[r] * HDIM + (tid & 7) * 4;
    }
    const float* bptr = Wu + (size_t)e * HDIM * IDIM + n0;

    float acc[4][4][4];
#pragma unroll
    for (int i = 0; i < 4; i++)
#pragma unroll
        for (int j = 0; j < 4; j++)
#pragma unroll
            for (int q = 0; q < 4; q++) acc[i][j][q] = 0.f;

    GemmCore::run(sm + 128, sm + 128 + A_FL, aptr, bptr, IDIM,
                  HDIM / KC, tid, wid, lane, acc);

    const int m0w = (wid >> 2) * 64;
    const int n0w = (wid & 3) * 32;
#pragma unroll
    for (int mt = 0; mt < 4; mt++) {
        int rloc = m0w + mt * 16 + (lane >> 2);
#pragma unroll
        for (int h = 0; h < 2; h++) {
            int m = m0 + rloc + h * 8;
            if (m < ne) {
                const float* grow = g_raw + (size_t)(off + m) * IDIM + n0;
                float* orow = g_act + (size_t)(off + m) * IDIM + n0;
#pragma unroll
                for (int nt = 0; nt < 4; nt++) {
                    int c = n0w + nt * 8 + 2 * (lane & 3);
                    float2 gv = *(const float2*)(grow + c);
                    float2 v;
                    v.x = gv.x / (1.f + expf(-gv.x)) * acc[mt][nt][2 * h];
                    v.y = gv.y / (1.f + expf(-gv.y)) * acc[mt][nt][2 * h + 1];
                    *(float2*)(orow + c) = v;
                }
            }
        }
    }
}

// ---------------- down GEMM: g_pairout = wt * (g_act @ Wd) ----------------
__global__ __launch_bounds__(256, 2) void down_tc(const float* __restrict__ Wd) {
    extern __shared__ float sm[];
    const int e = blockIdx.z;
    const int ne = g_off[e + 1] - g_off[e];
    const int m0 = blockIdx.y * BMT;
    if (m0 >= ne) return;
    const int n0 = blockIdx.x * BNT;
    const int off = g_off[e];

    const int tid = threadIdx.x;
    const int wid = tid >> 5;
    const int lane = tid & 31;

    const float* aptr[4];
#pragma unroll
    for (int i = 0; i < 4; i++) {
        int r = i * 32 + (tid >> 3);
        int idx = off + m0 + r;
        if (idx >= NPAIR) idx = NPAIR - 1;
        aptr[i] = g_act + (size_t)idx * IDIM + (tid & 7) * 4;
    }
    const float* bptr = Wd + (size_t)e * IDIM * HDIM + n0;

    float acc[4][4][4];
#pragma unroll
    for (int i = 0; i < 4; i++)
#pragma unroll
        for (int j = 0; j < 4; j++)
#pragma unroll
            for (int q = 0; q < 4; q++) acc[i][j][q] = 0.f;

    GemmCore::run(sm + 128, sm + 128 + A_FL, aptr, bptr, HDIM,
                  IDIM / KC, tid, wid, lane, acc);

    const int m0w = (wid >> 2) * 64;
    const int n0w = (wid & 3) * 32;
#pragma unroll
    for (int mt = 0; mt < 4; mt++) {
        int rloc = m0w + mt * 16 + (lane >> 2);
#pragma unroll
        for (int h = 0; h < 2; h++) {
            int m = m0 + rloc + h * 8;
            if (m < ne) {
                float wt = g_wt[off + m];
                float* orow = g_pairout + (size_t)(off + m) * HDIM + n0;
#pragma unroll
                for (int nt = 0; nt < 4; nt++) {
                    int c = n0w + nt * 8 + 2 * (lane & 3);
                    float2 v;
                    v.x = wt * acc[mt][nt][2 * h];
                    v.y = wt * acc[mt][nt][2 * h + 1];
                    *(float2*)(orow + c) = v;
                }
            }
        }
    }
}

// out[t, :] = pairout[p0, :] + pairout[p1, :]
__global__ void combine_kernel(float* __restrict__ out) {
    int idx = blockIdx.x * blockDim.x + threadIdx.x;
    int t = idx >> 8;
    int h4 = idx & 255;
    int p0 = g_tokpair[t * 2 + 0];
    int p1 = g_tokpair[t * 2 + 1];
    const float4* po = (const float4*)g_pairout;
    float4 a = po[(size_t)p0 * 256 + h4];
    float4 b = po[(size_t)p1 * 256 + h4];
    float4 r;
    r.x = a.x + b.x; r.y = a.y + b.y; r.z = a.z + b.z; r.w = a.w + b.w;
    ((float4*)out)[idx] = r;
}

// ---------------- launch ----------------
extern "C" void kernel_launch(void* const* d_in, const int* in_sizes, int n_in,
                              void* d_out, int out_size) {
    const float* x  = (const float*)d_in[0];
    const float* gw = (const float*)d_in[1];
    const float* Wg = (const float*)d_in[2];
    const float* Wu = (const float*)d_in[3];
    const float* Wd = (const float*)d_in[4];
    float* out = (float*)d_out;
    float* out_logits = out + (size_t)T_TOK * HDIM;

    cudaFuncSetAttribute(gate_tc, cudaFuncAttributeMaxDynamicSharedMemorySize, GEMM_SMEM);
    cudaFuncSetAttribute(up_tc, cudaFuncAttributeMaxDynamicSharedMemorySize, GEMM_SMEM);
    cudaFuncSetAttribute(down_tc, cudaFuncAttributeMaxDynamicSharedMemorySize, GEMM_SMEM);

    router_kernel<<<T_TOK, 128>>>(x, gw, out_logits);
    scan_kernel<<<1, 1>>>();
    assign_kernel<<<T_TOK / 256, 256>>>();
    gate_tc<<<dim3(IDIM / BNT, NPAIR / BMT, EDIM), 256, GEMM_SMEM>>>(x, Wg);
    up_tc<<<dim3(IDIM / BNT, NPAIR / BMT, EDIM), 256, GEMM_SMEM>>>(x, Wu);
    down_tc<<<dim3(HDIM / BNT, NPAIR / BMT, EDIM), 256, GEMM_SMEM>>>(Wd);
    combine_kernel<<<(T_TOK * HDIM / 4) / 256, 256>>>(out);
}